// round 17
// baseline (speedup 1.0000x reference)
#include <cuda_runtime.h>
#include <cuda_bf16.h>
#include <cstdint>

#define GENE   2000
#define TE     128
#define HID    2048
#define KIN    2128      // GENE + TE (time embedding lives in x tail)
#define NSTEP  256
#define GRID   128
#define BLOCK  512
#define NCOL   16        // output columns per CTA
#define DT     (1.0f/255.0f)
#define SLAB_BYTES (HID*NCOL*2)             // 64 KB resident slab per layer
#define SMEM_BYTES (2*SLAB_BYTES)           // 128 KB (slabs only)

// Permuted bf16 weights: per-CTA slice contiguous.
#define OFF0   0L
#define OFF1   (OFF0 + 128L*KIN*NCOL)
#define OFF2   (OFF1 + 128L*HID*NCOL)
#define OFF3   (OFF2 + 128L*HID*NCOL)
#define OFF4   (OFF3 + 128L*HID*NCOL)
#define OFFO   (OFF4 + 128L*HID*NCOL)
#define TOTALF (OFFO + 125L*HID*NCOL)       // ~25.2M bf16 = ~48 MB (L2-resident)

// Persistent scratch (device globals: allocation is forbidden)
__device__ __nv_bfloat16 g_wrep[TOTALF];
__device__ float    g_x[2][2176];      // x ping-pong: [0,2000)=x, [2000,2128)=te(t)
__device__ float    g_h0[HID];
__device__ float    g_h1[HID];
__device__ float    g_te[NSTEP][TE];
__device__ unsigned g_count;           // flat barrier counter (red-based)

// ---------------------------------------------------------------------------
// Decentralized flat barrier. Wait: EVERY thread polls (one coalesced
// request per warp; warps proceed independently on detect — no post-detect
// CTA sync). Arrive: warp0 only, after __syncwarp (orders lanes' h stores
// before lane0's release; cross-warp stores are ordered by the preceding
// reduce __syncthreads).
// ---------------------------------------------------------------------------
__device__ __forceinline__ void bar_wait(unsigned nbar) {
    if (nbar) {
        const unsigned target = nbar * GRID;
        unsigned cur;
        do {
            asm volatile("ld.acquire.gpu.u32 %0, [%1];"
                         : "=r"(cur) : "l"(&g_count) : "memory");
        } while (cur < target);
    }
}
__device__ __forceinline__ void bar_publish(int tid) {
    if (tid < 32) {
        __syncwarp();
        if (tid == 0)
            asm volatile("red.release.gpu.add.u32 [%0], 1;"
                         :: "l"(&g_count) : "memory");
    }
}

// 8-col MAC on one 32-byte weight row held in a register uint4.
__device__ __forceinline__ void mac8u(float* acc, uint4 wv, float xv) {
    const float2 f0 = __bfloat1622float2(*reinterpret_cast<const __nv_bfloat162*>(&wv.x));
    const float2 f1 = __bfloat1622float2(*reinterpret_cast<const __nv_bfloat162*>(&wv.y));
    const float2 f2 = __bfloat1622float2(*reinterpret_cast<const __nv_bfloat162*>(&wv.z));
    const float2 f3 = __bfloat1622float2(*reinterpret_cast<const __nv_bfloat162*>(&wv.w));
    acc[0] = fmaf(xv, f0.x, acc[0]);
    acc[1] = fmaf(xv, f0.y, acc[1]);
    acc[2] = fmaf(xv, f1.x, acc[2]);
    acc[3] = fmaf(xv, f1.y, acc[3]);
    acc[4] = fmaf(xv, f2.x, acc[4]);
    acc[5] = fmaf(xv, f2.y, acc[5]);
    acc[6] = fmaf(xv, f3.x, acc[6]);
    acc[7] = fmaf(xv, f3.y, acc[7]);
}

// Load one layer's per-thread weight rows (uint4 each) into registers.
template<int NROWN>
__device__ __forceinline__ void load_w(uint4* wv, const char* slice, int K,
                                       int kw, int jv, bool act) {
    if (act) {
        #pragma unroll
        for (int i = 0; i < NROWN; ++i) {
            const int r = kw + i*256;
            if (NROWN == 8 || r < K)
                wv[i] = __ldg(reinterpret_cast<const uint4*>(slice + (long)r*32 + jv*16));
        }
    }
}

// Cross-thread reduction (shfl + one smem round + ONE __syncthreads).
// Returns the column sum for tid<16 (col j0+tid).
__device__ __forceinline__ float reduce_tail(float* acc, float (*red2)[2][8], int tid) {
    #pragma unroll
    for (int m = 2; m <= 16; m <<= 1) {
        #pragma unroll
        for (int k = 0; k < 8; ++k)
            acc[k] += __shfl_xor_sync(0xffffffffu, acc[k], m);
    }
    const int warp = tid >> 5;
    const int lane = tid & 31;
    if (lane < 2) {
        #pragma unroll
        for (int k = 0; k < 8; ++k) red2[warp][lane][k] = acc[k];
    }
    __syncthreads();          // the ONLY intra-CTA sync per layer
    float r = 0.f;
    if (tid < NCOL) {
        const int cj = tid >> 3;
        const int ck = tid & 7;
        #pragma unroll
        for (int w = 0; w < 16; ++w)
            r += red2[w][cj][ck];
    }
    return r;
}

// ---------------------------------------------------------------------------
// Register-weight layer core: wait, x loads, MACs on pre-loaded register
// weights, prefetch next register layer's weights, reduce.
// ---------------------------------------------------------------------------
template<int NROW, int NROWN>
__device__ __forceinline__ float reg_layer(
    uint4* wv, const float* __restrict__ in, int K, bool act,
    const char* __restrict__ slicen, int Kn, bool actn,
    float (*red2)[2][8], int tid, unsigned nbar)
{
    bar_wait(nbar);

    const int kw = tid >> 1;
    const int jv = tid & 1;

    float xv[NROW];
    #pragma unroll
    for (int i = 0; i < NROW; ++i) {
        const int r = kw + i*256;
        xv[i] = (NROW == 8 || r < K) ? __ldcg(in + r) : 0.f;
    }

    float acc[8];
    #pragma unroll
    for (int k = 0; k < 8; ++k) acc[k] = 0.f;

    if (act) {
        #pragma unroll
        for (int i = 0; i < NROW; ++i) {
            const int r = kw + i*256;
            if (NROW == 8 || r < K)
                mac8u(acc, wv[i], xv[i]);
        }
    }
    load_w<NROWN>(wv, slicen, Kn, kw, jv, actn);   // regs reusable now

    return reduce_tail(acc, red2, tid);
}

// ---------------------------------------------------------------------------
// Resident layer: weights in SMEM slabs.
// ---------------------------------------------------------------------------
__device__ __forceinline__ float resident_layer(
    const char* __restrict__ wres, const float* __restrict__ in,
    float (*red2)[2][8], int tid, unsigned nbar)
{
    bar_wait(nbar);

    const int kw = tid >> 1;
    const int jv = tid & 1;

    float xv[8];
    #pragma unroll
    for (int i = 0; i < 8; ++i)
        xv[i] = __ldcg(in + kw + i*256);

    float acc[8];
    #pragma unroll
    for (int k = 0; k < 8; ++k) acc[k] = 0.f;

    #pragma unroll
    for (int i = 0; i < 8; ++i) {
        const uint4 w = *reinterpret_cast<const uint4*>(wres + (long)(kw + i*256)*32 + jv*16);
        mac8u(acc, w, xv[i]);
    }
    return reduce_tail(acc, red2, tid);
}

// ---------------------------------------------------------------------------
// Setup kernel: weight reorg (y = 0..5) + barrier/x0/te init (y = 6).
// ---------------------------------------------------------------------------
__global__ void setup_kernel(
    const float* __restrict__ w0, const float* __restrict__ w1,
    const float* __restrict__ w2, const float* __restrict__ w3,
    const float* __restrict__ w4, const float* __restrict__ wout,
    const float* __restrict__ start,
    const float* __restrict__ te_w1, const float* __restrict__ te_b1,
    const float* __restrict__ te_w2, const float* __restrict__ te_b2,
    float* __restrict__ out)
{
    const int b = blockIdx.x;   // 0..127
    const int l = blockIdx.y;   // 0..6

    if (l < 6) {                // ---- weight reorg ----
        const float* W; int K, O; long off;
        switch (l) {
            case 0: W = w0;   K = KIN; O = HID;  off = OFF0; break;
            case 1: W = w1;   K = HID; O = HID;  off = OFF1; break;
            case 2: W = w2;   K = HID; O = HID;  off = OFF2; break;
            case 3: W = w3;   K = HID; O = HID;  off = OFF3; break;
            case 4: W = w4;   K = HID; O = HID;  off = OFF4; break;
            default:W = wout; K = HID; O = GENE; off = OFFO; break;
        }
        const int j0 = b * NCOL;
        if (j0 >= O) return;
        __nv_bfloat16* dst = g_wrep + off + (long)b * K * NCOL;
        const int n4 = K * (NCOL/4);
        for (int e = threadIdx.x; e < n4; e += blockDim.x) {
            const int r  = e >> 2;
            const int c4 = (e & 3) * 4;
            const float4 w = *reinterpret_cast<const float4*>(W + (long)r * O + j0 + c4);
            uint2 p;
            __nv_bfloat162 p0 = __float22bfloat162_rn(make_float2(w.x, w.y));
            __nv_bfloat162 p1 = __float22bfloat162_rn(make_float2(w.z, w.w));
            p.x = *reinterpret_cast<unsigned*>(&p0);
            p.y = *reinterpret_cast<unsigned*>(&p1);
            *reinterpret_cast<uint2*>(dst + (long)e * 4) = p;
        }
    } else {                    // ---- init: t = 2b and 2b+1 ----
        __shared__ float h[2][TE];
        const int half = threadIdx.x >> 7;       // 0 or 1
        const int lane = threadIdx.x & 127;
        const int t    = 2*b + half;
        const float tt = (float)t * DT;
        h[half][lane] = fmaxf(fmaf(tt, te_w1[lane], te_b1[lane]), 0.f);
        __syncthreads();
        float acc = te_b2[lane];
        #pragma unroll 8
        for (int k = 0; k < TE; ++k)
            acc = fmaf(h[half][k], te_w2[k * TE + lane], acc);
        if (t >= 1) {
            g_te[t][lane] = acc;
            if (t == 1) g_x[0][GENE + lane] = acc;   // te(1) tail for step 1
        } else {                // t == 0: barrier reset + x0 seed + row 0
            if (lane == 0) g_count = 0u;
            for (int k = lane; k < GENE; k += TE) {
                const float v = start[k];
                g_x[0][k] = v;
                out[k]    = v;
            }
        }
    }
}

// ---------------------------------------------------------------------------
// Persistent kernel: 255 Euler steps, 6 flat decentralized barriers/step.
// Layers 1-2 from SMEM slabs; layers 0,3,4,out with register-resident
// weights (cross-barrier prefetch). Biases in registers; te tail stored by
// warp 15 during the output layer (ordered by the reduce syncthreads).
// ---------------------------------------------------------------------------
__global__ void __launch_bounds__(BLOCK, 1) bridge_kernel(
    const float* __restrict__ b0, const float* __restrict__ b1,
    const float* __restrict__ b2, const float* __restrict__ b3,
    const float* __restrict__ b4, const float* __restrict__ bout,
    float* __restrict__ out)
{
    extern __shared__ float smem[];
    char* rw1 = reinterpret_cast<char*>(smem);          // resident w1 slab
    char* rw2 = rw1 + SLAB_BYTES;                       // resident w2 slab
    __shared__ float red2[16][2][8];

    const int tid = threadIdx.x;
    const int b   = blockIdx.x;
    const int j0  = b * NCOL;
    const bool actO = (j0 < GENE);
    const int kw = tid >> 1;
    const int jv = tid & 1;

    const char* s0 = reinterpret_cast<const char*>(g_wrep + OFF0 + (long)b * KIN * NCOL);
    const char* s1 = reinterpret_cast<const char*>(g_wrep + OFF1 + (long)b * HID * NCOL);
    const char* s2 = reinterpret_cast<const char*>(g_wrep + OFF2 + (long)b * HID * NCOL);
    const char* s3 = reinterpret_cast<const char*>(g_wrep + OFF3 + (long)b * HID * NCOL);
    const char* s4 = reinterpret_cast<const char*>(g_wrep + OFF4 + (long)b * HID * NCOL);
    const char* so = reinterpret_cast<const char*>(g_wrep + OFFO + (long)b * HID * NCOL);

    // Hoisted biases (one per owned column, tid<16).
    float bb0 = 0.f, bb1 = 0.f, bb2 = 0.f, bb3 = 0.f, bb4 = 0.f, bbo = 0.f;
    if (tid < NCOL) {
        bb0 = __ldg(b0 + j0 + tid);
        bb1 = __ldg(b1 + j0 + tid);
        bb2 = __ldg(b2 + j0 + tid);
        bb3 = __ldg(b3 + j0 + tid);
        bb4 = __ldg(b4 + j0 + tid);
        if (actO) bbo = __ldg(bout + j0 + tid);
    }

    // Prologue: resident slabs into smem (drained by the first layer's
    // reduce __syncthreads, before any slab read), layer0 weights into regs.
    for (int i = tid; i < SLAB_BYTES/16; i += BLOCK)
        *reinterpret_cast<uint4*>(rw1 + i*16) =
            __ldg(reinterpret_cast<const uint4*>(s1 + (long)i*16));
    for (int i = tid; i < SLAB_BYTES/16; i += BLOCK)
        *reinterpret_cast<uint4*>(rw2 + i*16) =
            __ldg(reinterpret_cast<const uint4*>(s2 + (long)i*16));

    uint4 wv[9];
    load_w<9>(wv, s0, KIN, kw, jv, true);

    unsigned nbar = 0;

    for (int t = 1; t < NSTEP; ++t) {
        const float* xprev = g_x[(t - 1) & 1];
        float*       xcur  = g_x[t & 1];
        float r;

        // Layer 0 (consume s0, prefetch s3)
        r = reg_layer<9,8>(wv, xprev, KIN, true,  s3, HID, true, red2, tid, nbar);
        if (tid < NCOL) g_h0[j0 + tid] = fmaxf(r + bb0, 0.f);
        ++nbar; bar_publish(tid);

        // xprev[j] is stable this whole step — preload for the Euler tail.
        float xp = 0.f;
        if (tid < NCOL && actO) xp = __ldcg(xprev + j0 + tid);

        r = resident_layer(rw1, g_h0, red2, tid, nbar);
        if (tid < NCOL) g_h1[j0 + tid] = fmaxf(r + bb1, 0.f);
        ++nbar; bar_publish(tid);

        r = resident_layer(rw2, g_h1, red2, tid, nbar);
        if (tid < NCOL) g_h0[j0 + tid] = fmaxf(r + bb2, 0.f);
        ++nbar; bar_publish(tid);

        // Layer 3 (consume s3, prefetch s4)
        r = reg_layer<8,8>(wv, g_h0, HID, true,  s4, HID, true, red2, tid, nbar);
        if (tid < NCOL) g_h1[j0 + tid] = fmaxf(r + bb3, 0.f);
        ++nbar; bar_publish(tid);

        // Layer 4 (consume s4, prefetch so)
        r = reg_layer<8,8>(wv, g_h1, HID, true,  so, HID, actO, red2, tid, nbar);
        if (tid < NCOL) g_h0[j0 + tid] = fmaxf(r + bb4, 0.f);
        ++nbar; bar_publish(tid);

        // Output layer (consume so, prefetch s0). te tail stored by warp 15
        // BEFORE the reduce sync (ordered ahead of the arrival by it).
        {
            bar_wait(nbar);
            float xvv[8];
            #pragma unroll
            for (int i = 0; i < 8; ++i)
                xvv[i] = __ldcg(g_h0 + kw + i*256);
            float acc[8];
            #pragma unroll
            for (int k = 0; k < 8; ++k) acc[k] = 0.f;
            if (actO) {
                #pragma unroll
                for (int i = 0; i < 8; ++i)
                    mac8u(acc, wv[i], xvv[i]);
            }
            load_w<9>(wv, s0, KIN, kw, jv, true);

            // te(t+1) tail install (warp 15, off the warp0 critical tail)
            if (b == GRID - 1 && t + 1 < NSTEP && tid >= 480 && tid < 480 + NCOL) {
                const int lane = tid - 480;
                #pragma unroll
                for (int i = 0; i < 8; ++i) {
                    const int e = lane + i*NCOL;
                    xcur[GENE + e] = __ldg(&g_te[t + 1][e]);
                }
            }

            r = reduce_tail(acc, red2, tid);
        }
        if (tid < NCOL && actO) {
            const int j = j0 + tid;
            const float xn = fmaf(r + bbo, DT, xp);
            xcur[j] = xn;
            __stcs(out + (size_t)t * GENE + j, xn);
        }
        ++nbar; bar_publish(tid);
    }
}

extern "C" void kernel_launch(void* const* d_in, const int* in_sizes, int n_in,
                              void* d_out, int out_size)
{
    (void)in_sizes; (void)n_in; (void)out_size;
    const float* start  = (const float*)d_in[0];
    // d_in[1] = end_state (unused)
    const float* te_w1  = (const float*)d_in[2];
    const float* te_b1  = (const float*)d_in[3];
    const float* te_w2  = (const float*)d_in[4];
    const float* te_b2  = (const float*)d_in[5];
    const float* w0     = (const float*)d_in[6];
    const float* b0     = (const float*)d_in[7];
    const float* w1     = (const float*)d_in[8];
    const float* b1     = (const float*)d_in[9];
    const float* w2     = (const float*)d_in[10];
    const float* b2     = (const float*)d_in[11];
    const float* w3     = (const float*)d_in[12];
    const float* b3     = (const float*)d_in[13];
    const float* w4     = (const float*)d_in[14];
    const float* b4     = (const float*)d_in[15];
    const float* wout   = (const float*)d_in[16];
    const float* bout   = (const float*)d_in[17];
    float* out = (float*)d_out;

    cudaFuncSetAttribute(bridge_kernel,
                         cudaFuncAttributeMaxDynamicSharedMemorySize, SMEM_BYTES);

    dim3 sg(GRID, 7);
    setup_kernel<<<sg, 256>>>(w0, w1, w2, w3, w4, wout,
                              start, te_w1, te_b1, te_w2, te_b2, out);
    bridge_kernel<<<GRID, BLOCK, SMEM_BYTES>>>(b0, b1, b2, b3, b4, bout, out);
}